// round 11
// baseline (speedup 1.0000x reference)
#include <cuda_runtime.h>
#include <cuda_fp16.h>
#include <math.h>

#define Nn 10000
#define Ee 160000
#define NT 8192          // radial table resolution over [0, 10]

// prep kernel block partition
#define NB_INIT 2500     // Nn/4 node-init blocks
#define NB_GEOM 625      // Ee/256 geometry blocks
#define NB_TAB  2048     // NT/4 tabulation blocks

// ---------- device scratch ----------
__device__ float  g_emb[Nn * 64];
__device__ __half g_h0h[Nn * 64];
__device__ __half g_h1h[Nn * 64];
__device__ float  g_nf1[Nn * 64];
__device__ __half g_T0h[NT * 64];
__device__ __half g_T1h[NT * 64];
__device__ float2 g_rx [Ee];
__device__ int    g_cnt[Nn];        // statically zero; re-zeroed by scan each call
__device__ int    g_off[Nn + 1];
__device__ int    g_pos[Nn];
__device__ uint2  g_es [Ee];        // packed (sender | i0<<14, frac bits)

typedef unsigned long long u64;

__device__ __forceinline__ u64 pack2(float lo, float hi) {
    u64 r; asm("mov.b64 %0, {%1, %2};" : "=l"(r) : "f"(lo), "f"(hi)); return r;
}
__device__ __forceinline__ void unpack2(u64 v, float &a, float &b) {
    asm("mov.b64 {%0, %1}, %2;" : "=f"(a), "=f"(b) : "l"(v));
}
__device__ __forceinline__ void fma2(u64 &d, u64 a, u64 b) {
    asm("fma.rn.f32x2 %0, %1, %2, %0;" : "+l"(d) : "l"(a), "l"(b));
}
__device__ __forceinline__ float silu_f(float x) {
    return x / (1.0f + __expf(-x));
}

// ---------- fused prep: node-init | edge geometry + histogram | tabulation ----------
__global__ void __launch_bounds__(256)
prep_kernel(const float* __restrict__ attrs,
            const float* __restrict__ w_embed,
            const float* __restrict__ u0_up,
            const float* __restrict__ pos,
            const float* __restrict__ shifts,
            const int*   __restrict__ snd,
            const int*   __restrict__ rcv,
            const float* __restrict__ W1a, const float* __restrict__ W2a,
            const float* __restrict__ W3a,
            const float* __restrict__ W1b, const float* __restrict__ W2b,
            const float* __restrict__ W3b)
{
    __shared__ float sbuf[4992];
    int tid = threadIdx.x;
    int blk = blockIdx.x;

    if (blk < NB_INIT) {
        // ---- node init: emb = attrs @ w_embed ; h0 = emb @ u0_up ----
        float* sUp  = sbuf;          // 4096
        float* sWe  = sbuf + 4096;   // 640
        float* semb = sbuf + 4736;   // 256
        for (int i = tid; i < 4096; i += 256) sUp[i] = u0_up[i];
        for (int i = tid; i < 640;  i += 256) sWe[i] = w_embed[i];
        __syncthreads();

        int n = blk * 4 + (tid >> 6);
        int g = tid & 63;

        float v = 0.f;
#pragma unroll
        for (int s = 0; s < 10; s++)
            v += attrs[n * 10 + s] * sWe[s * 64 + g];
        semb[tid] = v;
        g_emb[n * 64 + g] = v;
        __syncthreads();

        const float* se = &semb[tid & 192];
        float h = 0.f;
#pragma unroll 8
        for (int f = 0; f < 64; f++)
            h += se[f] * sUp[f * 64 + g];
        g_h0h[n * 64 + g] = __float2half(h);

    } else if (blk < NB_INIT + NB_GEOM) {
        // ---- geometry + receiver histogram ----
        int e = (blk - NB_INIT) * 256 + tid;
        int s = snd[e];
        int r = rcv[e];
        float dx = pos[3 * r + 0] - pos[3 * s + 0] + shifts[3 * e + 0];
        float dy = pos[3 * r + 1] - pos[3 * s + 1] + shifts[3 * e + 1];
        float dz = pos[3 * r + 2] - pos[3 * s + 2] + shifts[3 * e + 2];
        float rr = sqrtf(dx * dx + dy * dy + dz * dz);

        float t  = rr * ((float)NT / 10.0f);
        int   i0 = (int)t;
        if (i0 > NT - 2) i0 = NT - 2;
        float fr = t - (float)i0;
        g_rx[e] = make_float2(__int_as_float(i0), fr);
        atomicAdd(&g_cnt[r], 1);

    } else {
        // ---- tabulate radial MLP (l=0 channel): 4 grid points per block ----
        int sub = tid >> 6;
        int f   = tid & 63;
        int p   = (blk - NB_INIT - NB_GEOM) * 4 + sub;
        float* l1 = sbuf + sub * 128;
        float* t2 = l1 + 64;

        float rr = (float)p * (10.0f / (float)NT);
        float inv = 1.0f / (rr + 1e-9f);
        float xr  = rr * 0.1f;
        float xr2 = xr * xr;
        float x5  = xr2 * xr2 * xr;
        float env = 1.0f - 21.0f * x5 + 35.0f * x5 * xr - 15.0f * x5 * xr2;
        if (xr >= 1.0f) env = 0.0f;
        float scl   = 0.44721359549995793f * inv * env;
        float theta = 3.14159265358979323846f * xr;

        float b[8];
#pragma unroll
        for (int k = 0; k < 8; k++)
            b[k] = scl * sinf((float)(k + 1) * theta);

#pragma unroll 1
        for (int phase = 0; phase < 2; phase++) {
            const float* W1 = phase ? W1b : W1a;
            const float* W2 = phase ? W2b : W2a;
            const float* W3 = phase ? W3b : W3a;
            __half* T = phase ? g_T1h : g_T0h;

            float v = 0.f;
#pragma unroll
            for (int k = 0; k < 8; k++)
                v += b[k] * W1[k * 64 + f];
            l1[f] = silu_f(v);
            __syncthreads();

            float w = 0.f;
#pragma unroll 8
            for (int i = 0; i < 64; i++)
                w += l1[i] * W2[i * 64 + f];
            t2[f] = silu_f(w);
            __syncthreads();

            float o = 0.f;
#pragma unroll 8
            for (int j = 0; j < 64; j++)
                o += t2[j] * W3[j * 256 + 4 * f];   // l=0 column
            T[p * 64 + f] = __float2half(o);
            __syncthreads();
        }
    }
}

// ---------- CSR offsets: 1-block exclusive scan of g_cnt; re-zero g_cnt ----------
__global__ void __launch_bounds__(1024)
scan_kernel()
{
    __shared__ int ssum[1024];
    int tid = threadIdx.x;
    int base = tid * 10;

    int c[10];
    int run = 0;
#pragma unroll
    for (int k = 0; k < 10; k++) {
        int idx = base + k;
        int v = (idx < Nn) ? g_cnt[idx] : 0;
        c[k] = run;
        run += v;
    }
    ssum[tid] = run;
    __syncthreads();

    for (int off = 1; off < 1024; off <<= 1) {
        int t = (tid >= off) ? ssum[tid - off] : 0;
        __syncthreads();
        ssum[tid] += t;
        __syncthreads();
    }
    int excl = ssum[tid] - run;

#pragma unroll
    for (int k = 0; k < 10; k++) {
        int idx = base + k;
        if (idx < Nn) {
            int o = excl + c[k];
            g_off[idx] = o;
            g_pos[idx] = o;
            g_cnt[idx] = 0;      // reset for next kernel_launch call
        }
    }
    if (tid == 0) g_off[Nn] = Ee;
}

// ---------- scatter: pack (sender, table idx, frac) into receiver-sorted list ----------
__global__ void __launch_bounds__(256)
scatter_kernel(const int* __restrict__ snd, const int* __restrict__ rcv)
{
    int e = blockIdx.x * 256 + threadIdx.x;
    int s = snd[e];
    int r = rcv[e];
    float2 rx = g_rx[e];
    int i0 = __float_as_int(rx.x);
    int pos = atomicAdd(&g_pos[r], 1);
    g_es[pos] = make_uint2((unsigned)s | ((unsigned)i0 << 14),
                           __float_as_uint(rx.y));
}

// ---------- interaction-0: gather + epilogue + out0 + h1 (warp per node) ----------
__global__ void __launch_bounds__(256)
node1_kernel(const float* __restrict__ attrs,
             const float* __restrict__ u0_mix,
             const float* __restrict__ u0_sc,
             const float* __restrict__ u0_prod,
             const float* __restrict__ w_read0,
             const float* __restrict__ u1_up,
             float* __restrict__ out)
{
    __shared__ float sMix[4096];
    __shared__ float sUp1[4096];
    __shared__ float sA[512], semb[512], snf[512];

    int tid = threadIdx.x;
    for (int i = tid; i < 4096; i += 256) sMix[i] = u0_mix[i];
    for (int i = tid; i < 4096; i += 256) sUp1[i] = u1_up[i];
    for (int i = tid; i < 512; i += 256)
        semb[i] = g_emb[blockIdx.x * 512 + i];

    int w  = tid >> 5;            // node within block (8 nodes/block)
    int l  = tid & 31;
    int g0 = 2 * l;
    int n  = blockIdx.x * 8 + w;
    int L  = w * 64;

    // ---- gather messages for node n: A[g] = sum_e h0[s_e][g] * lerp(T0)[g] ----
    int beg = g_off[n];
    int end = g_off[n + 1];
    float ax = 0.f, ay = 0.f;
    uint2 se = (beg < end) ? g_es[beg] : make_uint2(0u, 0u);
    for (int i = beg; i < end; i++) {
        uint2 cur = se;
        if (i + 1 < end) se = g_es[i + 1];
        int   s  = cur.x & 16383;
        int   i0 = cur.x >> 14;
        float fr = __uint_as_float(cur.y);
        float2 ta = __half22float2(*(const __half2*)&g_T0h[i0 * 64 + g0]);
        float2 tb = __half22float2(*(const __half2*)&g_T0h[(i0 + 1) * 64 + g0]);
        float2 h  = __half22float2(*(const __half2*)&g_h0h[s * 64 + g0]);
        ax += h.x * (ta.x + fr * (tb.x - ta.x));
        ay += h.y * (ta.y + fr * (tb.y - ta.y));
    }
    __syncthreads();              // staging of sMix/sUp1/semb complete
    sA[L + g0]     = ax * (1.0f / 16.0f);
    sA[L + g0 + 1] = ay * (1.0f / 16.0f);
    __syncwarp(0xffffffffu);

    int sp = 0;
#pragma unroll
    for (int s = 0; s < 10; s++)
        if (attrs[n * 10 + s] > 0.5f) sp = s;

    const float* Wsc = u0_sc + sp * 4096;
    u64 am2 = 0ull, sc2 = 0ull;
#pragma unroll 8
    for (int f = 0; f < 64; f++) {
        float a  = sA[L + f];
        float e2 = semb[L + f];
        float2 wm = *(const float2*)&sMix[f * 64 + g0];
        float2 ws = *(const float2*)&Wsc[f * 64 + g0];
        fma2(am2, pack2(a, a),   pack2(wm.x, wm.y));
        fma2(sc2, pack2(e2, e2), pack2(ws.x, ws.y));
    }
    float am0, am1, sc0, sc1;
    unpack2(am2, am0, am1);
    unpack2(sc2, sc0, sc1);

    float2 p0 = *(const float2*)&u0_prod[g0];
    float2 p1 = *(const float2*)&u0_prod[64 + g0];
    float2 p2 = *(const float2*)&u0_prod[128 + g0];
    float nf0 = am0 * (p0.x + p1.x * am0 + p2.x * am0 * am0) + sc0;
    float nf1 = am1 * (p0.y + p1.y * am1 + p2.y * am1 * am1) + sc1;

    *(float2*)&g_nf1[n * 64 + g0] = make_float2(nf0, nf1);
    *(float2*)&snf[L + g0]        = make_float2(nf0, nf1);

    // out0: warp-complete reduction
    float2 wr = *(const float2*)&w_read0[g0];
    float red = nf0 * wr.x + nf1 * wr.y;
#pragma unroll
    for (int o = 16; o > 0; o >>= 1)
        red += __shfl_down_sync(0xffffffffu, red, o);
    if (l == 0) out[n * 2 + 0] = red;
    __syncwarp(0xffffffffu);

    u64 h2 = 0ull;
#pragma unroll 8
    for (int f = 0; f < 64; f++) {
        float a = snf[L + f];
        float2 wu = *(const float2*)&sUp1[f * 64 + g0];
        fma2(h2, pack2(a, a), pack2(wu.x, wu.y));
    }
    float h0v, h1v;
    unpack2(h2, h0v, h1v);
    *(__half2*)&g_h1h[n * 64 + g0] = __floats2half2_rn(h0v, h1v);
}

// ---------- interaction-1: gather + epilogue + out1 (warp per node) ----------
__global__ void __launch_bounds__(256)
node2_kernel(const float* __restrict__ attrs,
             const float* __restrict__ u1_mix,
             const float* __restrict__ u1_sc,
             const float* __restrict__ u1_prod,
             const float* __restrict__ w_mlp1,
             const float* __restrict__ w_mlp2,
             float* __restrict__ out)
{
    __shared__ float sMix[4096];
    __shared__ float sM1[1024];
    __shared__ float sA[512], snf1[512], snf2[512];

    int tid = threadIdx.x;
    for (int i = tid; i < 4096; i += 256) sMix[i] = u1_mix[i];
    for (int i = tid; i < 1024; i += 256) sM1[i]  = w_mlp1[i];
    for (int i = tid; i < 512; i += 256)
        snf1[i] = g_nf1[blockIdx.x * 512 + i];

    int w  = tid >> 5;
    int l  = tid & 31;
    int g0 = 2 * l;
    int n  = blockIdx.x * 8 + w;
    int L  = w * 64;

    // ---- gather messages for node n (interaction 1) ----
    int beg = g_off[n];
    int end = g_off[n + 1];
    float ax = 0.f, ay = 0.f;
    uint2 se = (beg < end) ? g_es[beg] : make_uint2(0u, 0u);
    for (int i = beg; i < end; i++) {
        uint2 cur = se;
        if (i + 1 < end) se = g_es[i + 1];
        int   s  = cur.x & 16383;
        int   i0 = cur.x >> 14;
        float fr = __uint_as_float(cur.y);
        float2 ta = __half22float2(*(const __half2*)&g_T1h[i0 * 64 + g0]);
        float2 tb = __half22float2(*(const __half2*)&g_T1h[(i0 + 1) * 64 + g0]);
        float2 h  = __half22float2(*(const __half2*)&g_h1h[s * 64 + g0]);
        ax += h.x * (ta.x + fr * (tb.x - ta.x));
        ay += h.y * (ta.y + fr * (tb.y - ta.y));
    }
    __syncthreads();
    sA[L + g0]     = ax * (1.0f / 16.0f);
    sA[L + g0 + 1] = ay * (1.0f / 16.0f);
    __syncwarp(0xffffffffu);

    int sp = 0;
#pragma unroll
    for (int s = 0; s < 10; s++)
        if (attrs[n * 10 + s] > 0.5f) sp = s;

    const float* Wsc = u1_sc + sp * 4096;
    u64 am2 = 0ull, sc2 = 0ull;
#pragma unroll 8
    for (int f = 0; f < 64; f++) {
        float a  = sA[L + f];
        float e2 = snf1[L + f];
        float2 wm = *(const float2*)&sMix[f * 64 + g0];
        float2 ws = *(const float2*)&Wsc[f * 64 + g0];
        fma2(am2, pack2(a, a),   pack2(wm.x, wm.y));
        fma2(sc2, pack2(e2, e2), pack2(ws.x, ws.y));
    }
    float am0, am1, sc0, sc1;
    unpack2(am2, am0, am1);
    unpack2(sc2, sc0, sc1);

    float2 p0 = *(const float2*)&u1_prod[g0];
    float2 p1 = *(const float2*)&u1_prod[64 + g0];
    float2 p2 = *(const float2*)&u1_prod[128 + g0];
    float nf0 = am0 * (p0.x + p1.x * am0 + p2.x * am0 * am0) + sc0;
    float nf1 = am1 * (p0.y + p1.y * am1 + p2.y * am1 * am1) + sc1;
    *(float2*)&snf2[L + g0] = make_float2(nf0, nf1);
    __syncwarp(0xffffffffu);

    // out1: 16-wide hidden layer, lanes 0..15, warp-local
    float red = 0.f;
    if (l < 16) {
        float hv = 0.f;
#pragma unroll 8
        for (int f = 0; f < 64; f++)
            hv += snf2[L + f] * sM1[f * 16 + l];
        red = silu_f(hv) * w_mlp2[l];
    }
#pragma unroll
    for (int o = 8; o > 0; o >>= 1)
        red += __shfl_down_sync(0xffffffffu, red, o, 16);
    if (l == 0) out[n * 2 + 1] = red;
}

extern "C" void kernel_launch(void* const* d_in, const int* in_sizes, int n_in,
                              void* d_out, int out_size)
{
    const float* positions  = (const float*)d_in[0];
    const float* node_attrs = (const float*)d_in[1];
    const float* shifts     = (const float*)d_in[2];
    const int*   senders    = (const int*)  d_in[3];
    const int*   receivers  = (const int*)  d_in[4];
    const float* w_embed    = (const float*)d_in[5];

    int i_u0 = 6, i_u1, i_read0, i_mlp1, i_mlp2;
    if (in_sizes[13] == 64) {        // signature order
        i_read0 = 13; i_u1 = 14; i_mlp1 = 21; i_mlp2 = 22;
    } else {                          // dict order
        i_u1 = 13; i_read0 = 20; i_mlp1 = 21; i_mlp2 = 22;
    }

    const float* u0_up   = (const float*)d_in[i_u0 + 0];
    const float* u0_r1   = (const float*)d_in[i_u0 + 1];
    const float* u0_r2   = (const float*)d_in[i_u0 + 2];
    const float* u0_r3   = (const float*)d_in[i_u0 + 3];
    const float* u0_mix  = (const float*)d_in[i_u0 + 4];
    const float* u0_sc   = (const float*)d_in[i_u0 + 5];
    const float* u0_prod = (const float*)d_in[i_u0 + 6];
    const float* u1_up   = (const float*)d_in[i_u1 + 0];
    const float* u1_r1   = (const float*)d_in[i_u1 + 1];
    const float* u1_r2   = (const float*)d_in[i_u1 + 2];
    const float* u1_r3   = (const float*)d_in[i_u1 + 3];
    const float* u1_mix  = (const float*)d_in[i_u1 + 4];
    const float* u1_sc   = (const float*)d_in[i_u1 + 5];
    const float* u1_prod = (const float*)d_in[i_u1 + 6];
    const float* w_read0 = (const float*)d_in[i_read0];
    const float* w_mlp1  = (const float*)d_in[i_mlp1];
    const float* w_mlp2  = (const float*)d_in[i_mlp2];

    float* out = (float*)d_out;

    prep_kernel<<<NB_INIT + NB_GEOM + NB_TAB, 256>>>(
        node_attrs, w_embed, u0_up, positions, shifts, senders, receivers,
        u0_r1, u0_r2, u0_r3, u1_r1, u1_r2, u1_r3);
    scan_kernel<<<1, 1024>>>();
    scatter_kernel<<<Ee / 256, 256>>>(senders, receivers);
    node1_kernel<<<Nn / 8, 256>>>(node_attrs, u0_mix, u0_sc, u0_prod,
                                  w_read0, u1_up, out);
    node2_kernel<<<Nn / 8, 256>>>(node_attrs, u1_mix, u1_sc, u1_prod,
                                  w_mlp1, w_mlp2, out);
}

// round 12
// speedup vs baseline: 1.3442x; 1.3442x over previous
#include <cuda_runtime.h>
#include <cuda_fp16.h>
#include <math.h>

#define Nn 10000
#define Ee 160000
#define NT 8192          // radial table resolution over [0, 10]

// prep kernel block partition
#define NB_INIT 625      // 16 nodes/block
#define NB_GEOM 625      // Ee/256
#define NB_TAB  2048     // NT/4
#define NB_SC0  10       // one block per species

// ---------- device scratch ----------
__device__ __half g_h0h[Nn * 64];
__device__ __half g_h1h[Nn * 64];
__device__ float  g_A0 [Nn * 64];
__device__ float  g_A1 [Nn * 64];
__device__ float  g_nf1[Nn * 64];
__device__ __half g_T0h[NT * 64];
__device__ __half g_T1h[NT * 64];
__device__ float2 g_rx [Ee];
__device__ int    g_sp [Nn];
__device__ float  g_sc0[10 * 64];

typedef unsigned long long u64;

__device__ __forceinline__ u64 pack2(float lo, float hi) {
    u64 r; asm("mov.b64 %0, {%1, %2};" : "=l"(r) : "f"(lo), "f"(hi)); return r;
}
__device__ __forceinline__ void unpack2(u64 v, float &a, float &b) {
    asm("mov.b64 {%0, %1}, %2;" : "=f"(a), "=f"(b) : "l"(v));
}
__device__ __forceinline__ void fma2(u64 &d, u64 a, u64 b) {
    asm("fma.rn.f32x2 %0, %1, %2, %0;" : "+l"(d) : "l"(a), "l"(b));
}
__device__ __forceinline__ void red4(float* p, float a, float b, float c, float d) {
    asm volatile("red.global.add.v4.f32 [%0], {%1, %2, %3, %4};"
                 :: "l"(p), "f"(a), "f"(b), "f"(c), "f"(d) : "memory");
}
__device__ __forceinline__ float silu_f(float x) {
    return x / (1.0f + __expf(-x));
}

// ---------- fused prep: init(one-hot tables) | geometry | tabulation | sc0 ----------
__global__ void __launch_bounds__(256)
prep_kernel(const float* __restrict__ attrs,
            const float* __restrict__ w_embed,
            const float* __restrict__ u0_up,
            const float* __restrict__ u0_sc,
            const float* __restrict__ pos,
            const float* __restrict__ shifts,
            const int*   __restrict__ snd,
            const int*   __restrict__ rcv,
            const float* __restrict__ W1a, const float* __restrict__ W2a,
            const float* __restrict__ W3a,
            const float* __restrict__ W1b, const float* __restrict__ W2b,
            const float* __restrict__ W3b)
{
    __shared__ float sbuf[5392];
    int tid = threadIdx.x;
    int blk = blockIdx.x;

    if (blk < NB_INIT) {
        // ---- init: species lookup; h0 = (w_embed @ u0_up)[sp]; zero A ----
        float* sWe = sbuf;             // 640
        float* sUp = sbuf + 640;       // 4096
        float* tab = sbuf + 4736;      // 640
        int*   ssp = (int*)(sbuf + 5376);  // 16

        for (int i = tid; i < 640;  i += 256) sWe[i] = w_embed[i];
        for (int i = tid; i < 4096; i += 256) sUp[i] = u0_up[i];
        if (tid < 16) {
            int n = blk * 16 + tid;
            int sp = 0;
#pragma unroll
            for (int s = 0; s < 10; s++)
                if (attrs[n * 10 + s] > 0.5f) sp = s;
            ssp[tid] = sp;
            g_sp[n] = sp;
        }
        __syncthreads();

        for (int idx = tid; idx < 640; idx += 256) {
            int sp = idx >> 6, g = idx & 63;
            float v = 0.f;
#pragma unroll 8
            for (int f = 0; f < 64; f++)
                v += sWe[sp * 64 + f] * sUp[f * 64 + g];
            tab[idx] = v;
        }
        __syncthreads();

        for (int idx = tid; idx < 1024; idx += 256) {
            int nl = idx >> 6, g = idx & 63;
            g_h0h[(blk * 16 + nl) * 64 + g] = __float2half(tab[ssp[nl] * 64 + g]);
        }
        for (int idx = tid; idx < 1024; idx += 256) {
            g_A0[blk * 1024 + idx] = 0.f;
            g_A1[blk * 1024 + idx] = 0.f;
        }

    } else if (blk < NB_INIT + NB_GEOM) {
        // ---- geometry: r -> (table index, frac) ----
        int e = (blk - NB_INIT) * 256 + tid;
        int s = snd[e];
        int r = rcv[e];
        float dx = pos[3 * r + 0] - pos[3 * s + 0] + shifts[3 * e + 0];
        float dy = pos[3 * r + 1] - pos[3 * s + 1] + shifts[3 * e + 1];
        float dz = pos[3 * r + 2] - pos[3 * s + 2] + shifts[3 * e + 2];
        float rr = sqrtf(dx * dx + dy * dy + dz * dz);

        float t  = rr * ((float)NT / 10.0f);
        int   i0 = (int)t;
        if (i0 > NT - 2) i0 = NT - 2;
        float fr = t - (float)i0;
        g_rx[e] = make_float2(__int_as_float(i0), fr);

    } else if (blk < NB_INIT + NB_GEOM + NB_TAB) {
        // ---- tabulate radial MLP (l=0 channel): 4 grid points per block ----
        int sub = tid >> 6;
        int f   = tid & 63;
        int p   = (blk - NB_INIT - NB_GEOM) * 4 + sub;
        float* l1 = sbuf + sub * 128;
        float* t2 = l1 + 64;

        float rr = (float)p * (10.0f / (float)NT);
        float inv = 1.0f / (rr + 1e-9f);
        float xr  = rr * 0.1f;
        float xr2 = xr * xr;
        float x5  = xr2 * xr2 * xr;
        float env = 1.0f - 21.0f * x5 + 35.0f * x5 * xr - 15.0f * x5 * xr2;
        if (xr >= 1.0f) env = 0.0f;
        float scl   = 0.44721359549995793f * inv * env;
        float theta = 3.14159265358979323846f * xr;

        float b[8];
#pragma unroll
        for (int k = 0; k < 8; k++)
            b[k] = scl * sinf((float)(k + 1) * theta);

#pragma unroll 1
        for (int phase = 0; phase < 2; phase++) {
            const float* W1 = phase ? W1b : W1a;
            const float* W2 = phase ? W2b : W2a;
            const float* W3 = phase ? W3b : W3a;
            __half* T = phase ? g_T1h : g_T0h;

            float v = 0.f;
#pragma unroll
            for (int k = 0; k < 8; k++)
                v += b[k] * W1[k * 64 + f];
            l1[f] = silu_f(v);
            __syncthreads();

            float w = 0.f;
#pragma unroll 8
            for (int i = 0; i < 64; i++)
                w += l1[i] * W2[i * 64 + f];
            t2[f] = silu_f(w);
            __syncthreads();

            float o = 0.f;
#pragma unroll 8
            for (int j = 0; j < 64; j++)
                o += t2[j] * W3[j * 256 + 4 * f];   // l=0 column
            T[p * 64 + f] = __float2half(o);
            __syncthreads();
        }
    } else {
        // ---- sc0 table: sc0[k,g] = sum_f w_embed[k,f] * u0_sc[k,f,g] ----
        int k = blk - NB_INIT - NB_GEOM - NB_TAB;
        if (tid < 64) {
            int g = tid;
            const float* S = u0_sc + k * 4096;
            float v = 0.f;
#pragma unroll 8
            for (int f = 0; f < 64; f++)
                v += w_embed[k * 64 + f] * S[f * 64 + g];
            g_sc0[k * 64 + g] = v;
        }
    }
}

// ---------- edge message pass: fp16 table + fp16 h, fp32 math + fp32 RED ----------
template <int PHASE>
__global__ void __launch_bounds__(256)
edge_pass(const int* __restrict__ snd, const int* __restrict__ rcv)
{
    unsigned idx = blockIdx.x * 256u + threadIdx.x;   // Ee*16 threads
    int e = idx >> 4;
    int q = (idx & 15) * 4;

    int s = snd[e];
    int r = rcv[e];
    float2 rx = g_rx[e];
    int   i0 = __float_as_int(rx.x);
    float fr = rx.y;

    const __half* T = PHASE ? g_T1h : g_T0h;
    const __half* H = PHASE ? g_h1h : g_h0h;
    float*        A = PHASE ? g_A1  : g_A0;

    uint2 va = *(const uint2*)&T[i0 * 64 + q];
    uint2 vb = *(const uint2*)&T[(i0 + 1) * 64 + q];
    uint2 vh = *(const uint2*)&H[s * 64 + q];

    float2 ta0 = __half22float2(*(const __half2*)&va.x);
    float2 ta1 = __half22float2(*(const __half2*)&va.y);
    float2 tb0 = __half22float2(*(const __half2*)&vb.x);
    float2 tb1 = __half22float2(*(const __half2*)&vb.y);
    float2 h0  = __half22float2(*(const __half2*)&vh.x);
    float2 h1  = __half22float2(*(const __half2*)&vh.y);

    float R0 = ta0.x + fr * (tb0.x - ta0.x);
    float R1 = ta0.y + fr * (tb0.y - ta0.y);
    float R2 = ta1.x + fr * (tb1.x - ta1.x);
    float R3 = ta1.y + fr * (tb1.y - ta1.y);

    red4(&A[r * 64 + q], h0.x * R0, h0.y * R1, h1.x * R2, h1.y * R3);
}

// ---------- interaction-0 epilogue + out0 + h1 : warp/node, 16 nodes/block ----------
__global__ void __launch_bounds__(512)
node1_kernel(const float* __restrict__ u0_mix,
             const float* __restrict__ u0_prod,
             const float* __restrict__ w_read0,
             const float* __restrict__ u1_up,
             float* __restrict__ out)
{
    __shared__ float sMix[4096];
    __shared__ float sUp1[4096];
    __shared__ float sA[1024], snf[1024];

    int tid = threadIdx.x;
    for (int i = tid; i < 4096; i += 512) sMix[i] = u0_mix[i];
    for (int i = tid; i < 4096; i += 512) sUp1[i] = u1_up[i];
    for (int i = tid; i < 1024; i += 512)
        sA[i] = g_A0[blockIdx.x * 1024 + i] * (1.0f / 16.0f);
    __syncthreads();

    int w  = tid >> 5;            // node within block (16 nodes/block)
    int l  = tid & 31;
    int g0 = 2 * l;
    int n  = blockIdx.x * 16 + w;
    int L  = w * 64;

    int sp = g_sp[n];

    u64 am2 = 0ull;
#pragma unroll 8
    for (int f = 0; f < 64; f++) {
        float a  = sA[L + f];
        float2 wm = *(const float2*)&sMix[f * 64 + g0];
        fma2(am2, pack2(a, a), pack2(wm.x, wm.y));
    }
    float am0, am1;
    unpack2(am2, am0, am1);

    float2 sc = *(const float2*)&g_sc0[sp * 64 + g0];
    float2 p0 = *(const float2*)&u0_prod[g0];
    float2 p1 = *(const float2*)&u0_prod[64 + g0];
    float2 p2 = *(const float2*)&u0_prod[128 + g0];
    float nf0 = am0 * (p0.x + p1.x * am0 + p2.x * am0 * am0) + sc.x;
    float nf1 = am1 * (p0.y + p1.y * am1 + p2.y * am1 * am1) + sc.y;

    *(float2*)&g_nf1[n * 64 + g0] = make_float2(nf0, nf1);
    *(float2*)&snf[L + g0]        = make_float2(nf0, nf1);

    // out0: warp-complete reduction
    float2 wr = *(const float2*)&w_read0[g0];
    float red = nf0 * wr.x + nf1 * wr.y;
#pragma unroll
    for (int o = 16; o > 0; o >>= 1)
        red += __shfl_down_sync(0xffffffffu, red, o);
    if (l == 0) out[n * 2 + 0] = red;
    __syncwarp(0xffffffffu);

    u64 h2 = 0ull;
#pragma unroll 8
    for (int f = 0; f < 64; f++) {
        float a = snf[L + f];
        float2 wu = *(const float2*)&sUp1[f * 64 + g0];
        fma2(h2, pack2(a, a), pack2(wu.x, wu.y));
    }
    float h0v, h1v;
    unpack2(h2, h0v, h1v);
    *(__half2*)&g_h1h[n * 64 + g0] = __floats2half2_rn(h0v, h1v);
}

// ---------- interaction-1 epilogue + out1 : warp/node, 16 nodes/block ----------
__global__ void __launch_bounds__(512)
node2_kernel(const float* __restrict__ u1_mix,
             const float* __restrict__ u1_sc,
             const float* __restrict__ u1_prod,
             const float* __restrict__ w_mlp1,
             const float* __restrict__ w_mlp2,
             float* __restrict__ out)
{
    __shared__ float sMix[4096];
    __shared__ float sM1[1024];
    __shared__ float sA[1024], snf1[1024], snf2[1024];

    int tid = threadIdx.x;
    for (int i = tid; i < 4096; i += 512) sMix[i] = u1_mix[i];
    for (int i = tid; i < 1024; i += 512) sM1[i]  = w_mlp1[i];
    for (int i = tid; i < 1024; i += 512) {
        sA[i]   = g_A1[blockIdx.x * 1024 + i] * (1.0f / 16.0f);
        snf1[i] = g_nf1[blockIdx.x * 1024 + i];
    }
    __syncthreads();

    int w  = tid >> 5;
    int l  = tid & 31;
    int g0 = 2 * l;
    int n  = blockIdx.x * 16 + w;
    int L  = w * 64;

    int sp = g_sp[n];

    const float* Wsc = u1_sc + sp * 4096;
    u64 am2 = 0ull, sc2 = 0ull;
#pragma unroll 8
    for (int f = 0; f < 64; f++) {
        float a  = sA[L + f];
        float e2 = snf1[L + f];
        float2 wm = *(const float2*)&sMix[f * 64 + g0];
        float2 ws = *(const float2*)&Wsc[f * 64 + g0];
        fma2(am2, pack2(a, a),   pack2(wm.x, wm.y));
        fma2(sc2, pack2(e2, e2), pack2(ws.x, ws.y));
    }
    float am0, am1, sc0, sc1;
    unpack2(am2, am0, am1);
    unpack2(sc2, sc0, sc1);

    float2 p0 = *(const float2*)&u1_prod[g0];
    float2 p1 = *(const float2*)&u1_prod[64 + g0];
    float2 p2 = *(const float2*)&u1_prod[128 + g0];
    float nf0 = am0 * (p0.x + p1.x * am0 + p2.x * am0 * am0) + sc0;
    float nf1 = am1 * (p0.y + p1.y * am1 + p2.y * am1 * am1) + sc1;
    *(float2*)&snf2[L + g0] = make_float2(nf0, nf1);
    __syncwarp(0xffffffffu);

    // out1: 16-wide hidden layer, lanes 0..15, warp-local
    float red = 0.f;
    if (l < 16) {
        float hv = 0.f;
#pragma unroll 8
        for (int f = 0; f < 64; f++)
            hv += snf2[L + f] * sM1[f * 16 + l];
        red = silu_f(hv) * w_mlp2[l];
    }
#pragma unroll
    for (int o = 8; o > 0; o >>= 1)
        red += __shfl_down_sync(0xffffffffu, red, o, 16);
    if (l == 0) out[n * 2 + 1] = red;
}

extern "C" void kernel_launch(void* const* d_in, const int* in_sizes, int n_in,
                              void* d_out, int out_size)
{
    const float* positions  = (const float*)d_in[0];
    const float* node_attrs = (const float*)d_in[1];
    const float* shifts     = (const float*)d_in[2];
    const int*   senders    = (const int*)  d_in[3];
    const int*   receivers  = (const int*)  d_in[4];
    const float* w_embed    = (const float*)d_in[5];

    int i_u0 = 6, i_u1, i_read0, i_mlp1, i_mlp2;
    if (in_sizes[13] == 64) {        // signature order
        i_read0 = 13; i_u1 = 14; i_mlp1 = 21; i_mlp2 = 22;
    } else {                          // dict order
        i_u1 = 13; i_read0 = 20; i_mlp1 = 21; i_mlp2 = 22;
    }

    const float* u0_up   = (const float*)d_in[i_u0 + 0];
    const float* u0_r1   = (const float*)d_in[i_u0 + 1];
    const float* u0_r2   = (const float*)d_in[i_u0 + 2];
    const float* u0_r3   = (const float*)d_in[i_u0 + 3];
    const float* u0_mix  = (const float*)d_in[i_u0 + 4];
    const float* u0_sc   = (const float*)d_in[i_u0 + 5];
    const float* u0_prod = (const float*)d_in[i_u0 + 6];
    const float* u1_up   = (const float*)d_in[i_u1 + 0];
    const float* u1_r1   = (const float*)d_in[i_u1 + 1];
    const float* u1_r2   = (const float*)d_in[i_u1 + 2];
    const float* u1_r3   = (const float*)d_in[i_u1 + 3];
    const float* u1_mix  = (const float*)d_in[i_u1 + 4];
    const float* u1_sc   = (const float*)d_in[i_u1 + 5];
    const float* u1_prod = (const float*)d_in[i_u1 + 6];
    const float* w_read0 = (const float*)d_in[i_read0];
    const float* w_mlp1  = (const float*)d_in[i_mlp1];
    const float* w_mlp2  = (const float*)d_in[i_mlp2];

    float* out = (float*)d_out;

    prep_kernel<<<NB_INIT + NB_GEOM + NB_TAB + NB_SC0, 256>>>(
        node_attrs, w_embed, u0_up, u0_sc, positions, shifts, senders, receivers,
        u0_r1, u0_r2, u0_r3, u1_r1, u1_r2, u1_r3);
    edge_pass<0><<<Ee * 16 / 256, 256>>>(senders, receivers);
    node1_kernel<<<Nn / 16, 512>>>(u0_mix, u0_prod, w_read0, u1_up, out);
    edge_pass<1><<<Ee * 16 / 256, 256>>>(senders, receivers);
    node2_kernel<<<Nn / 16, 512>>>(u1_mix, u1_sc, u1_prod, w_mlp1, w_mlp2, out);
}

// round 15
// speedup vs baseline: 1.8867x; 1.4036x over previous
#include <cuda_runtime.h>
#include <cuda_fp16.h>
#include <math.h>

#define Nn 10000
#define Ee 160000
#define NT 2048          // radial table resolution over [0, 10]

// prep kernel block partition (longest phases first)
#define NB_TAB  512      // NT/4
#define NB_GEOM 625      // Ee/256
#define NB_INIT 625      // 16 nodes/block
#define NB_SC0  10       // one block per species

// ---------- device scratch ----------
__device__ __half g_h0h[Nn * 64];
__device__ __half g_h1h[Nn * 64];
__device__ float  g_A0 [Nn * 64];
__device__ float  g_A1 [Nn * 64];
__device__ float  g_nf1[Nn * 64];
__device__ __half g_T0h[NT * 64];
__device__ __half g_T1h[NT * 64];
__device__ float2 g_rx [Ee];
__device__ int    g_sp [Nn];
__device__ float  g_sc0[10 * 64];

typedef unsigned long long u64;

__device__ __forceinline__ u64 pack2(float lo, float hi) {
    u64 r; asm("mov.b64 %0, {%1, %2};" : "=l"(r) : "f"(lo), "f"(hi)); return r;
}
__device__ __forceinline__ void unpack2(u64 v, float &a, float &b) {
    asm("mov.b64 {%0, %1}, %2;" : "=f"(a), "=f"(b) : "l"(v));
}
__device__ __forceinline__ void fma2(u64 &d, u64 a, u64 b) {
    asm("fma.rn.f32x2 %0, %1, %2, %0;" : "+l"(d) : "l"(a), "l"(b));
}
__device__ __forceinline__ void red4(float* p, float a, float b, float c, float d) {
    asm volatile("red.global.add.v4.f32 [%0], {%1, %2, %3, %4};"
                 :: "l"(p), "f"(a), "f"(b), "f"(c), "f"(d) : "memory");
}
__device__ __forceinline__ float silu_f(float x) {
    return x / (1.0f + __expf(-x));
}

// ---------- fused prep: tabulation | geometry | init(one-hot tables) | sc0 ----------
__global__ void __launch_bounds__(256)
prep_kernel(const float* __restrict__ attrs,
            const float* __restrict__ w_embed,
            const float* __restrict__ u0_up,
            const float* __restrict__ u0_sc,
            const float* __restrict__ pos,
            const float* __restrict__ shifts,
            const int*   __restrict__ snd,
            const int*   __restrict__ rcv,
            const float* __restrict__ W1a, const float* __restrict__ W2a,
            const float* __restrict__ W3a,
            const float* __restrict__ W1b, const float* __restrict__ W2b,
            const float* __restrict__ W3b)
{
    __shared__ float sbuf[5392];
    int tid = threadIdx.x;
    int blk = blockIdx.x;

    if (blk < NB_TAB) {
        // ---- tabulate radial MLP (l=0 channel): 4 grid points per block ----
        int sub = tid >> 6;
        int f   = tid & 63;
        int p   = blk * 4 + sub;
        float* l1 = sbuf + sub * 128;
        float* t2 = l1 + 64;

        float rr = (float)p * (10.0f / (float)NT);
        float inv = 1.0f / (rr + 1e-9f);
        float xr  = rr * 0.1f;
        float xr2 = xr * xr;
        float x5  = xr2 * xr2 * xr;
        float env = 1.0f - 21.0f * x5 + 35.0f * x5 * xr - 15.0f * x5 * xr2;
        if (xr >= 1.0f) env = 0.0f;
        float scl   = 0.44721359549995793f * inv * env;
        float theta = 3.14159265358979323846f * xr;

        float b[8];
#pragma unroll
        for (int k = 0; k < 8; k++)
            b[k] = scl * sinf((float)(k + 1) * theta);

#pragma unroll 1
        for (int phase = 0; phase < 2; phase++) {
            const float* W1 = phase ? W1b : W1a;
            const float* W2 = phase ? W2b : W2a;
            const float* W3 = phase ? W3b : W3a;
            __half* T = phase ? g_T1h : g_T0h;

            float v = 0.f;
#pragma unroll
            for (int k = 0; k < 8; k++)
                v += b[k] * W1[k * 64 + f];
            l1[f] = silu_f(v);
            __syncthreads();

            float w = 0.f;
#pragma unroll 8
            for (int i = 0; i < 64; i++)
                w += l1[i] * W2[i * 64 + f];
            t2[f] = silu_f(w);
            __syncthreads();

            float o = 0.f;
#pragma unroll 8
            for (int j = 0; j < 64; j++)
                o += t2[j] * W3[j * 256 + 4 * f];   // l=0 column
            T[p * 64 + f] = __float2half(o);
            __syncthreads();
        }

    } else if (blk < NB_TAB + NB_GEOM) {
        // ---- geometry: r -> (table index, frac) ----
        int e = (blk - NB_TAB) * 256 + tid;
        int s = snd[e];
        int r = rcv[e];
        float dx = pos[3 * r + 0] - pos[3 * s + 0] + shifts[3 * e + 0];
        float dy = pos[3 * r + 1] - pos[3 * s + 1] + shifts[3 * e + 1];
        float dz = pos[3 * r + 2] - pos[3 * s + 2] + shifts[3 * e + 2];
        float rr = sqrtf(dx * dx + dy * dy + dz * dz);

        float t  = rr * ((float)NT / 10.0f);
        int   i0 = (int)t;
        if (i0 > NT - 2) i0 = NT - 2;
        float fr = t - (float)i0;
        g_rx[e] = make_float2(__int_as_float(i0), fr);

    } else if (blk < NB_TAB + NB_GEOM + NB_INIT) {
        // ---- init: species lookup; h0 = (w_embed @ u0_up)[sp]; zero A ----
        int ib = blk - NB_TAB - NB_GEOM;
        float* sWe = sbuf;             // 640
        float* sUp = sbuf + 640;       // 4096
        float* tab = sbuf + 4736;      // 640
        int*   ssp = (int*)(sbuf + 5376);  // 16

        for (int i = tid; i < 640;  i += 256) sWe[i] = w_embed[i];
        for (int i = tid; i < 4096; i += 256) sUp[i] = u0_up[i];
        if (tid < 16) {
            int n = ib * 16 + tid;
            int sp = 0;
#pragma unroll
            for (int s = 0; s < 10; s++)
                if (attrs[n * 10 + s] > 0.5f) sp = s;
            ssp[tid] = sp;
            g_sp[n] = sp;
        }
        __syncthreads();

        for (int idx = tid; idx < 640; idx += 256) {
            int sp = idx >> 6, g = idx & 63;
            float v = 0.f;
#pragma unroll 8
            for (int f = 0; f < 64; f++)
                v += sWe[sp * 64 + f] * sUp[f * 64 + g];
            tab[idx] = v;
        }
        __syncthreads();

        for (int idx = tid; idx < 1024; idx += 256) {
            int nl = idx >> 6, g = idx & 63;
            g_h0h[(ib * 16 + nl) * 64 + g] = __float2half(tab[ssp[nl] * 64 + g]);
        }
        for (int idx = tid; idx < 1024; idx += 256) {
            g_A0[ib * 1024 + idx] = 0.f;
            g_A1[ib * 1024 + idx] = 0.f;
        }

    } else {
        // ---- sc0 table: sc0[k,g] = sum_f w_embed[k,f] * u0_sc[k,f,g] ----
        int k = blk - NB_TAB - NB_GEOM - NB_INIT;
        if (tid < 64) {
            int g = tid;
            const float* S = u0_sc + k * 4096;
            float v = 0.f;
#pragma unroll 8
            for (int f = 0; f < 64; f++)
                v += w_embed[k * 64 + f] * S[f * 64 + g];
            g_sc0[k * 64 + g] = v;
        }
    }
}

// ---------- edge message pass: fp16 table + fp16 h, fp32 math + fp32 RED ----------
template <int PHASE>
__global__ void __launch_bounds__(256)
edge_pass(const int* __restrict__ snd, const int* __restrict__ rcv)
{
    unsigned idx = blockIdx.x * 256u + threadIdx.x;   // Ee*16 threads
    int e = idx >> 4;
    int q = (idx & 15) * 4;

    int s = snd[e];
    int r = rcv[e];
    float2 rx = g_rx[e];
    int   i0 = __float_as_int(rx.x);
    float fr = rx.y;

    const __half* T = PHASE ? g_T1h : g_T0h;
    const __half* H = PHASE ? g_h1h : g_h0h;
    float*        A = PHASE ? g_A1  : g_A0;

    uint2 va = *(const uint2*)&T[i0 * 64 + q];
    uint2 vb = *(const uint2*)&T[(i0 + 1) * 64 + q];
    uint2 vh = *(const uint2*)&H[s * 64 + q];

    float2 ta0 = __half22float2(*(const __half2*)&va.x);
    float2 ta1 = __half22float2(*(const __half2*)&va.y);
    float2 tb0 = __half22float2(*(const __half2*)&vb.x);
    float2 tb1 = __half22float2(*(const __half2*)&vb.y);
    float2 h0  = __half22float2(*(const __half2*)&vh.x);
    float2 h1  = __half22float2(*(const __half2*)&vh.y);

    float R0 = ta0.x + fr * (tb0.x - ta0.x);
    float R1 = ta0.y + fr * (tb0.y - ta0.y);
    float R2 = ta1.x + fr * (tb1.x - ta1.x);
    float R3 = ta1.y + fr * (tb1.y - ta1.y);

    red4(&A[r * 64 + q], h0.x * R0, h0.y * R1, h1.x * R2, h1.y * R3);
}

// ---------- interaction-0 epilogue + out0 + h1 : warp/node, 16 nodes/block ----------
__global__ void __launch_bounds__(512)
node1_kernel(const float* __restrict__ u0_mix,
             const float* __restrict__ u0_prod,
             const float* __restrict__ w_read0,
             const float* __restrict__ u1_up,
             float* __restrict__ out)
{
    __shared__ float sMix[4096];
    __shared__ float sUp1[4096];
    __shared__ float sA[1024], snf[1024];

    int tid = threadIdx.x;
    for (int i = tid; i < 4096; i += 512) sMix[i] = u0_mix[i];
    for (int i = tid; i < 4096; i += 512) sUp1[i] = u1_up[i];
    for (int i = tid; i < 1024; i += 512)
        sA[i] = g_A0[blockIdx.x * 1024 + i] * (1.0f / 16.0f);
    __syncthreads();

    int w  = tid >> 5;            // node within block (16 nodes/block)
    int l  = tid & 31;
    int g0 = 2 * l;
    int n  = blockIdx.x * 16 + w;
    int L  = w * 64;

    int sp = g_sp[n];

    u64 am2 = 0ull;
#pragma unroll 8
    for (int f = 0; f < 64; f++) {
        float a  = sA[L + f];
        float2 wm = *(const float2*)&sMix[f * 64 + g0];
        fma2(am2, pack2(a, a), pack2(wm.x, wm.y));
    }
    float am0, am1;
    unpack2(am2, am0, am1);

    float2 sc = *(const float2*)&g_sc0[sp * 64 + g0];
    float2 p0 = *(const float2*)&u0_prod[g0];
    float2 p1 = *(const float2*)&u0_prod[64 + g0];
    float2 p2 = *(const float2*)&u0_prod[128 + g0];
    float nf0 = am0 * (p0.x + p1.x * am0 + p2.x * am0 * am0) + sc.x;
    float nf1 = am1 * (p0.y + p1.y * am1 + p2.y * am1 * am1) + sc.y;

    *(float2*)&g_nf1[n * 64 + g0] = make_float2(nf0, nf1);
    *(float2*)&snf[L + g0]        = make_float2(nf0, nf1);

    // out0: warp-complete reduction
    float2 wr = *(const float2*)&w_read0[g0];
    float red = nf0 * wr.x + nf1 * wr.y;
#pragma unroll
    for (int o = 16; o > 0; o >>= 1)
        red += __shfl_down_sync(0xffffffffu, red, o);
    if (l == 0) out[n * 2 + 0] = red;
    __syncwarp(0xffffffffu);

    u64 h2 = 0ull;
#pragma unroll 8
    for (int f = 0; f < 64; f++) {
        float a = snf[L + f];
        float2 wu = *(const float2*)&sUp1[f * 64 + g0];
        fma2(h2, pack2(a, a), pack2(wu.x, wu.y));
    }
    float h0v, h1v;
    unpack2(h2, h0v, h1v);
    *(__half2*)&g_h1h[n * 64 + g0] = __floats2half2_rn(h0v, h1v);
}

// ---------- interaction-1 epilogue + out1 : warp/node, 16 nodes/block ----------
__global__ void __launch_bounds__(512)
node2_kernel(const float* __restrict__ u1_mix,
             const float* __restrict__ u1_sc,
             const float* __restrict__ u1_prod,
             const float* __restrict__ w_mlp1,
             const float* __restrict__ w_mlp2,
             float* __restrict__ out)
{
    __shared__ float sMix[4096];
    __shared__ float sM1[1024];
    __shared__ float sA[1024], snf1[1024], snf2[1024];

    int tid = threadIdx.x;
    for (int i = tid; i < 4096; i += 512) sMix[i] = u1_mix[i];
    for (int i = tid; i < 1024; i += 512) sM1[i]  = w_mlp1[i];
    for (int i = tid; i < 1024; i += 512) {
        sA[i]   = g_A1[blockIdx.x * 1024 + i] * (1.0f / 16.0f);
        snf1[i] = g_nf1[blockIdx.x * 1024 + i];
    }
    __syncthreads();

    int w  = tid >> 5;
    int l  = tid & 31;
    int g0 = 2 * l;
    int n  = blockIdx.x * 16 + w;
    int L  = w * 64;

    int sp = g_sp[n];

    const float* Wsc = u1_sc + sp * 4096;
    u64 am2 = 0ull, sc2 = 0ull;
#pragma unroll 8
    for (int f = 0; f < 64; f++) {
        float a  = sA[L + f];
        float e2 = snf1[L + f];
        float2 wm = *(const float2*)&sMix[f * 64 + g0];
        float2 ws = *(const float2*)&Wsc[f * 64 + g0];
        fma2(am2, pack2(a, a),   pack2(wm.x, wm.y));
        fma2(sc2, pack2(e2, e2), pack2(ws.x, ws.y));
    }
    float am0, am1, sc0, sc1;
    unpack2(am2, am0, am1);
    unpack2(sc2, sc0, sc1);

    float2 p0 = *(const float2*)&u1_prod[g0];
    float2 p1 = *(const float2*)&u1_prod[64 + g0];
    float2 p2 = *(const float2*)&u1_prod[128 + g0];
    float nf0 = am0 * (p0.x + p1.x * am0 + p2.x * am0 * am0) + sc0;
    float nf1 = am1 * (p0.y + p1.y * am1 + p2.y * am1 * am1) + sc1;
    *(float2*)&snf2[L + g0] = make_float2(nf0, nf1);
    __syncwarp(0xffffffffu);

    // out1: 16-wide hidden layer, lanes 0..15, warp-local
    float red = 0.f;
    if (l < 16) {
        float hv = 0.f;
#pragma unroll 8
        for (int f = 0; f < 64; f++)
            hv += snf2[L + f] * sM1[f * 16 + l];
        red = silu_f(hv) * w_mlp2[l];
    }
#pragma unroll
    for (int o = 8; o > 0; o >>= 1)
        red += __shfl_down_sync(0xffffffffu, red, o, 16);
    if (l == 0) out[n * 2 + 1] = red;
}

extern "C" void kernel_launch(void* const* d_in, const int* in_sizes, int n_in,
                              void* d_out, int out_size)
{
    const float* positions  = (const float*)d_in[0];
    const float* node_attrs = (const float*)d_in[1];
    const float* shifts     = (const float*)d_in[2];
    const int*   senders    = (const int*)  d_in[3];
    const int*   receivers  = (const int*)  d_in[4];
    const float* w_embed    = (const float*)d_in[5];

    int i_u0 = 6, i_u1, i_read0, i_mlp1, i_mlp2;
    if (in_sizes[13] == 64) {        // signature order
        i_read0 = 13; i_u1 = 14; i_mlp1 = 21; i_mlp2 = 22;
    } else {                          // dict order
        i_u1 = 13; i_read0 = 20; i_mlp1 = 21; i_mlp2 = 22;
    }

    const float* u0_up   = (const float*)d_in[i_u0 + 0];
    const float* u0_r1   = (const float*)d_in[i_u0 + 1];
    const float* u0_r2   = (const float*)d_in[i_u0 + 2];
    const float* u0_r3   = (const float*)d_in[i_u0 + 3];
    const float* u0_mix  = (const float*)d_in[i_u0 + 4];
    const float* u0_sc   = (const float*)d_in[i_u0 + 5];
    const float* u0_prod = (const float*)d_in[i_u0 + 6];
    const float* u1_up   = (const float*)d_in[i_u1 + 0];
    const float* u1_r1   = (const float*)d_in[i_u1 + 1];
    const float* u1_r2   = (const float*)d_in[i_u1 + 2];
    const float* u1_r3   = (const float*)d_in[i_u1 + 3];
    const float* u1_mix  = (const float*)d_in[i_u1 + 4];
    const float* u1_sc   = (const float*)d_in[i_u1 + 5];
    const float* u1_prod = (const float*)d_in[i_u1 + 6];
    const float* w_read0 = (const float*)d_in[i_read0];
    const float* w_mlp1  = (const float*)d_in[i_mlp1];
    const float* w_mlp2  = (const float*)d_in[i_mlp2];

    float* out = (float*)d_out;

    prep_kernel<<<NB_TAB + NB_GEOM + NB_INIT + NB_SC0, 256>>>(
        node_attrs, w_embed, u0_up, u0_sc, positions, shifts, senders, receivers,
        u0_r1, u0_r2, u0_r3, u1_r1, u1_r2, u1_r3);
    edge_pass<0><<<Ee * 16 / 256, 256>>>(senders, receivers);
    node1_kernel<<<Nn / 16, 512>>>(u0_mix, u0_prod, w_read0, u1_up, out);
    edge_pass<1><<<Ee * 16 / 256, 256>>>(senders, receivers);
    node2_kernel<<<Nn / 16, 512>>>(u1_mix, u1_sc, u1_prod, w_mlp1, w_mlp2, out);
}